// round 6
// baseline (speedup 1.0000x reference)
#include <cuda_runtime.h>
#include <cuda_fp16.h>
#include <stdint.h>

// DAGNNConv: 10-hop normalized propagation + sigmoid-gated combination.
// N=100000, D=64, E=1300000 (incl self-loops), K=10.
// fp16 hop storage; SpMM 4 nodes/warp with LDG.128 gather + batched edge
// records; NEW: nodes assigned to warps in degree-sorted order (counting
// sort fused into the scan kernels) so warp max-degree ~= mean degree.

#define NNODES 100000
#define DIM    64
#define KHOPS  10
#define EMAX   1400000
#define SCAN_B 1024
#define DBINS  1024

__device__ int     g_deg[NNODES];
__device__ int     g_fill[NNODES];
__device__ float   g_norm[NNODES];
__device__ int     g_rowoff[NNODES + 1];
__device__ int     g_part[256];
__device__ int     g_hist[DBINS];     // degree histogram -> exclusive offsets
__device__ int     g_hfill[DBINS];
__device__ int     g_perm[NNODES];    // nodes in degree-sorted order
__device__ int2    g_edge[EMAX];                        // {src, bits(w)}
__device__ __half2 g_F16[(size_t)NNODES * 32];          // feats in fp16
__device__ __half2 g_H[(size_t)KHOPS * NNODES * 32];    // hop results, fp16

// ---------------------------------------------------------------------------
__global__ void k_zero() {
    int i = blockIdx.x * blockDim.x + threadIdx.x;
    if (i < NNODES) { g_deg[i] = 0; g_fill[i] = 0; }
    if (i < DBINS)  { g_hist[i] = 0; g_hfill[i] = 0; }
}

__global__ void k_count(const int* __restrict__ dst, int nE) {
    int e = blockIdx.x * blockDim.x + threadIdx.x;
    if (e >= nE) return;
    unsigned d = (unsigned)dst[e];
    if (d < NNODES) atomicAdd(&g_deg[d], 1);
}

// block-local exclusive scan of degrees; norm = deg^-0.5; degree histogram.
__global__ void k_scan1() {
    __shared__ int sh[SCAN_B];
    int idx = blockIdx.x * SCAN_B + threadIdx.x;
    int v = 0;
    if (idx < NNODES) {
        v = g_deg[idx];
        g_norm[idx] = rsqrtf((float)v);
        atomicAdd(&g_hist[min(v, DBINS - 1)], 1);
    }
    sh[threadIdx.x] = v;
    __syncthreads();
    for (int off = 1; off < SCAN_B; off <<= 1) {
        int t = (threadIdx.x >= off) ? sh[threadIdx.x - off] : 0;
        __syncthreads();
        sh[threadIdx.x] += t;
        __syncthreads();
    }
    int incl = sh[threadIdx.x];
    if (idx < NNODES) g_rowoff[idx] = incl - v;
    if (threadIdx.x == SCAN_B - 1) g_part[blockIdx.x] = incl;
}

// single block: exclusive scan of block partials AND of the degree histogram.
__global__ void k_scan2(int nb, int nE) {
    __shared__ int sh[SCAN_B];
    // scan histogram (DBINS == SCAN_B)
    int hv = g_hist[threadIdx.x];
    sh[threadIdx.x] = hv;
    __syncthreads();
    for (int off = 1; off < SCAN_B; off <<= 1) {
        int t = (threadIdx.x >= off) ? sh[threadIdx.x - off] : 0;
        __syncthreads();
        sh[threadIdx.x] += t;
        __syncthreads();
    }
    g_hist[threadIdx.x] = sh[threadIdx.x] - hv;   // exclusive offsets
    __syncthreads();
    // scan block partials (<=128)
    int pv = (threadIdx.x < nb) ? g_part[threadIdx.x] : 0;
    sh[threadIdx.x] = pv;
    __syncthreads();
    for (int off = 1; off < 128; off <<= 1) {
        int t = (threadIdx.x >= off && threadIdx.x < 128) ? sh[threadIdx.x - off] : 0;
        __syncthreads();
        if (threadIdx.x < 128) sh[threadIdx.x] += t;
        __syncthreads();
    }
    if (threadIdx.x < nb) g_part[threadIdx.x] = sh[threadIdx.x] - pv;
    if (threadIdx.x == 0) g_rowoff[NNODES] = nE;
}

// rowoff fixup + permutation scatter (counting sort by degree).
__global__ void k_scan3() {
    int idx = blockIdx.x * SCAN_B + threadIdx.x;
    if (idx >= NNODES) return;
    g_rowoff[idx] += g_part[blockIdx.x];
    int d = min(g_deg[idx], DBINS - 1);
    int pos = g_hist[d] + atomicAdd(&g_hfill[d], 1);
    g_perm[pos] = idx;
}

__global__ void k_scatter(const int* __restrict__ src,
                          const int* __restrict__ dst, int nE) {
    int e = blockIdx.x * blockDim.x + threadIdx.x;
    if (e >= nE) return;
    unsigned s = (unsigned)src[e];
    unsigned d = (unsigned)dst[e];
    if (s >= NNODES || d >= NNODES) return;
    int pos = g_rowoff[d] + atomicAdd(&g_fill[d], 1);
    if (pos < EMAX)
        g_edge[pos] = make_int2((int)s, __float_as_int(g_norm[s] * g_norm[d]));
}

// Convert feats fp32 -> fp16 (32 half2 per node).
__global__ void k_cvt(const float* __restrict__ feats) {
    int i = blockIdx.x * blockDim.x + threadIdx.x;
    if (i >= NNODES * 32) return;
    float2 f = *(const float2*)(feats + (size_t)i * 2);
    g_F16[i] = __floats2half2_rn(f.x, f.y);
}

// ---------------------------------------------------------------------------
// One hop. 4 degree-adjacent nodes per warp (via g_perm); 8 lanes per node;
// lane owns 8 channels (16B LDG.128 gather). Edge records batched 8-at-a-time
// per group via one coalesced LDG + shfl.
__global__ void __launch_bounds__(256)
k_spmm(int hop) {
    int warp = blockIdx.x * 8 + (threadIdx.x >> 5);
    int lane = threadIdx.x & 31;
    int sub  = lane & 7;
    int gb   = lane & 24;
    int slot = warp * 4 + (lane >> 3);
    int v    = g_perm[slot < NNODES ? slot : NNODES - 1];

    const uint4* __restrict__ prev = (const uint4*)(
        (hop == 0) ? g_F16 : (g_H + (size_t)(hop - 1) * NNODES * 32));
    uint4* __restrict__ cur = (uint4*)(g_H + (size_t)hop * NNODES * 32);

    int beg = g_rowoff[v];
    int deg = g_rowoff[v + 1] - beg;

    int maxdeg = deg;
#pragma unroll
    for (int o = 16; o; o >>= 1)
        maxdeg = max(maxdeg, __shfl_xor_sync(0xFFFFFFFFu, maxdeg, o));

    float a0 = 0.f, a1 = 0.f, a2 = 0.f, a3 = 0.f;
    float a4 = 0.f, a5 = 0.f, a6 = 0.f, a7 = 0.f;

    for (int base = 0; base < maxdeg; base += 8) {
        int idx = base + sub;
        int2 er = make_int2(0, 0);
        if (idx < deg) er = g_edge[beg + idx];

        int   srcs[8];
        float ws[8];
#pragma unroll
        for (int j = 0; j < 8; j++) {
            srcs[j] = __shfl_sync(0xFFFFFFFFu, er.x, gb + j);
            ws[j]   = __int_as_float(__shfl_sync(0xFFFFFFFFu, er.y, gb + j));
        }
#pragma unroll
        for (int j = 0; j < 8; j++) {
            if (base + j < deg) {
                uint4 raw = prev[(size_t)srcs[j] * 8 + sub];
                float2 f0 = __half22float2(*(const __half2*)&raw.x);
                float2 f1 = __half22float2(*(const __half2*)&raw.y);
                float2 f2 = __half22float2(*(const __half2*)&raw.z);
                float2 f3 = __half22float2(*(const __half2*)&raw.w);
                float w = ws[j];
                a0 = fmaf(w, f0.x, a0); a1 = fmaf(w, f0.y, a1);
                a2 = fmaf(w, f1.x, a2); a3 = fmaf(w, f1.y, a3);
                a4 = fmaf(w, f2.x, a4); a5 = fmaf(w, f2.y, a5);
                a6 = fmaf(w, f3.x, a6); a7 = fmaf(w, f3.y, a7);
            }
        }
    }

    uint4 o;
    *(__half2*)&o.x = __floats2half2_rn(a0, a1);
    *(__half2*)&o.y = __floats2half2_rn(a2, a3);
    *(__half2*)&o.z = __floats2half2_rn(a4, a5);
    *(__half2*)&o.w = __floats2half2_rn(a6, a7);
    cur[(size_t)v * 8 + sub] = o;
}

// ---------------------------------------------------------------------------
// Gate + combine. Warp per node; lane owns channels {2*lane, 2*lane+1}.
__global__ void __launch_bounds__(256)
k_gate(const float* __restrict__ feats, const float* __restrict__ s,
       float* __restrict__ out) {
    int v = blockIdx.x * 8 + (threadIdx.x >> 5);
    if (v >= NNODES) return;
    int lane = threadIdx.x & 31;

    float2 sv = *(const float2*)(s + 2 * lane);

    float2 h[KHOPS + 1];
    h[0] = *(const float2*)(feats + (size_t)v * DIM + 2 * lane);
#pragma unroll
    for (int k = 1; k <= KHOPS; k++)
        h[k] = __half22float2(
            g_H[(size_t)(k - 1) * NNODES * 32 + (size_t)v * 32 + lane]);

    float a0 = 0.f, a1 = 0.f;
#pragma unroll
    for (int k = 0; k <= KHOPS; k++) {
        float p = h[k].x * sv.x + h[k].y * sv.y;
#pragma unroll
        for (int o = 16; o; o >>= 1) p += __shfl_xor_sync(0xFFFFFFFFu, p, o);
        float g = 1.f / (1.f + __expf(-p));
        a0 = fmaf(g, h[k].x, a0);
        a1 = fmaf(g, h[k].y, a1);
    }
    float2 o2; o2.x = a0; o2.y = a1;
    *(float2*)(out + (size_t)v * DIM + 2 * lane) = o2;
}

// ---------------------------------------------------------------------------
extern "C" void kernel_launch(void* const* d_in, const int* in_sizes, int n_in,
                              void* d_out, int out_size) {
    const float* feats = (const float*)d_in[0];
    const float* s     = (const float*)d_in[1];
    const int*   src   = (const int*)d_in[2];
    const int*   dst   = (const int*)d_in[3];
    float*       out   = (float*)d_out;
    int nE = in_sizes[2];

    int nb = (NNODES + SCAN_B - 1) / SCAN_B;       // 98
    int eb = (nE + 255) / 256;
    int wb = (NNODES + 7) / 8;                     // 12500 (gate)
    int sb = (NNODES / 4 + 7) / 8;                 // 3125  (spmm)

    k_zero<<<(NNODES + 255) / 256, 256>>>();
    k_count<<<eb, 256>>>(dst, nE);
    k_scan1<<<nb, SCAN_B>>>();
    k_scan2<<<1, SCAN_B>>>(nb, nE);
    k_scan3<<<nb, SCAN_B>>>();
    k_scatter<<<eb, 256>>>(src, dst, nE);
    k_cvt<<<(NNODES * 32 + 255) / 256, 256>>>(feats);

    for (int hop = 0; hop < KHOPS; hop++)
        k_spmm<<<sb, 256>>>(hop);

    k_gate<<<wb, 256>>>(feats, s, out);
}

// round 7
// speedup vs baseline: 1.2937x; 1.2937x over previous
#include <cuda_runtime.h>
#include <cuda_fp16.h>
#include <stdint.h>

// DAGNNConv: 10-hop normalized propagation + sigmoid-gated combination.
// N=100000, D=64, E=1300000 (incl self-loops), K=10.
// fp16 hop storage; SpMM 4 nodes/warp (natural order), 8 lanes/node,
// LDG.128 row gather. R7: unconditional gathers (w=0 padding) for full
// MLP, software-pipelined edge-record loads, cvt fused into zero.

#define NNODES 100000
#define DIM    64
#define KHOPS  10
#define EMAX   1400000
#define SCAN_B 1024

__device__ int     g_deg[NNODES];
__device__ int     g_fill[NNODES];
__device__ float   g_norm[NNODES];
__device__ int     g_rowoff[NNODES + 1];
__device__ int     g_part[256];
__device__ int2    g_edge[EMAX];                        // {src, bits(w)}
__device__ __half2 g_F16[(size_t)NNODES * 32];          // feats in fp16
__device__ __half2 g_H[(size_t)KHOPS * NNODES * 32];    // hop results, fp16

// ---------------------------------------------------------------------------
// zero counters + convert feats fp32->fp16 (fused; grid covers NNODES*32)
__global__ void k_zero(const float* __restrict__ feats) {
    int i = blockIdx.x * blockDim.x + threadIdx.x;
    if (i < NNODES) { g_deg[i] = 0; g_fill[i] = 0; }
    if (i < NNODES * 32) {
        float2 f = *(const float2*)(feats + (size_t)i * 2);
        g_F16[i] = __floats2half2_rn(f.x, f.y);
    }
}

__global__ void k_count(const int* __restrict__ dst, int nE) {
    int e = blockIdx.x * blockDim.x + threadIdx.x;
    if (e >= nE) return;
    unsigned d = (unsigned)dst[e];
    if (d < NNODES) atomicAdd(&g_deg[d], 1);
}

__global__ void k_scan1() {
    __shared__ int sh[SCAN_B];
    int idx = blockIdx.x * SCAN_B + threadIdx.x;
    int v = (idx < NNODES) ? g_deg[idx] : 0;
    if (idx < NNODES) g_norm[idx] = rsqrtf((float)v);
    sh[threadIdx.x] = v;
    __syncthreads();
    for (int off = 1; off < SCAN_B; off <<= 1) {
        int t = (threadIdx.x >= off) ? sh[threadIdx.x - off] : 0;
        __syncthreads();
        sh[threadIdx.x] += t;
        __syncthreads();
    }
    int incl = sh[threadIdx.x];
    if (idx < NNODES) g_rowoff[idx] = incl - v;
    if (threadIdx.x == SCAN_B - 1) g_part[blockIdx.x] = incl;
}

__global__ void k_scan2(int nb, int nE) {
    __shared__ int sh[128];
    int v = (threadIdx.x < nb) ? g_part[threadIdx.x] : 0;
    sh[threadIdx.x] = v;
    __syncthreads();
    for (int off = 1; off < 128; off <<= 1) {
        int t = (threadIdx.x >= off) ? sh[threadIdx.x - off] : 0;
        __syncthreads();
        sh[threadIdx.x] += t;
        __syncthreads();
    }
    if (threadIdx.x < nb) g_part[threadIdx.x] = sh[threadIdx.x] - v;
    if (threadIdx.x == 0) g_rowoff[NNODES] = nE;
}

__global__ void k_scan3() {
    int idx = blockIdx.x * SCAN_B + threadIdx.x;
    if (idx < NNODES) g_rowoff[idx] += g_part[blockIdx.x];
}

__global__ void k_scatter(const int* __restrict__ src,
                          const int* __restrict__ dst, int nE) {
    int e = blockIdx.x * blockDim.x + threadIdx.x;
    if (e >= nE) return;
    unsigned s = (unsigned)src[e];
    unsigned d = (unsigned)dst[e];
    if (s >= NNODES || d >= NNODES) return;
    int pos = g_rowoff[d] + atomicAdd(&g_fill[d], 1);
    if (pos < EMAX)
        g_edge[pos] = make_int2((int)s, __float_as_int(g_norm[s] * g_norm[d]));
}

// ---------------------------------------------------------------------------
// One hop. 4 consecutive nodes per warp; 8 lanes per node; lane owns 8
// channels (16B). Edge records: one coalesced LDG per batch, pipelined one
// batch ahead. Gathers unconditional (padded edges have src=0, w=0).
__global__ void __launch_bounds__(256)
k_spmm(int hop) {
    int warp = blockIdx.x * 8 + (threadIdx.x >> 5);
    int lane = threadIdx.x & 31;
    int sub  = lane & 7;          // lane within 8-lane group
    int gb   = lane & 24;         // first lane of group
    int v    = warp * 4 + (lane >> 3);
    if (v >= NNODES) v = NNODES - 1;

    const uint4* __restrict__ prev = (const uint4*)(
        (hop == 0) ? g_F16 : (g_H + (size_t)(hop - 1) * NNODES * 32));
    uint4* __restrict__ cur = (uint4*)(g_H + (size_t)hop * NNODES * 32);

    int beg = g_rowoff[v];
    int deg = g_rowoff[v + 1] - beg;

    int maxdeg = deg;
#pragma unroll
    for (int o = 16; o; o >>= 1)
        maxdeg = max(maxdeg, __shfl_xor_sync(0xFFFFFFFFu, maxdeg, o));
    int nbatch = (maxdeg + 7) >> 3;

    float a0 = 0.f, a1 = 0.f, a2 = 0.f, a3 = 0.f;
    float a4 = 0.f, a5 = 0.f, a6 = 0.f, a7 = 0.f;

    // prefetch batch 0 records
    int2 er = make_int2(0, 0);
    if (sub < deg) er = g_edge[beg + sub];

    for (int b = 0; b < nbatch; b++) {
        // prefetch next batch's records before consuming this one
        int2 er_next = make_int2(0, 0);
        int nidx = (b + 1) * 8 + sub;
        if (b + 1 < nbatch && nidx < deg) er_next = g_edge[beg + nidx];

        int   srcs[8];
        float ws[8];
#pragma unroll
        for (int j = 0; j < 8; j++) {
            srcs[j] = __shfl_sync(0xFFFFFFFFu, er.x, gb + j);
            ws[j]   = __int_as_float(__shfl_sync(0xFFFFFFFFu, er.y, gb + j));
        }
        // unconditional gathers: padded edges read row 0 (L1-hot), w=0
        uint4 raws[8];
#pragma unroll
        for (int j = 0; j < 8; j++)
            raws[j] = prev[(size_t)srcs[j] * 8 + sub];
#pragma unroll
        for (int j = 0; j < 8; j++) {
            float2 f0 = __half22float2(*(const __half2*)&raws[j].x);
            float2 f1 = __half22float2(*(const __half2*)&raws[j].y);
            float2 f2 = __half22float2(*(const __half2*)&raws[j].z);
            float2 f3 = __half22float2(*(const __half2*)&raws[j].w);
            float w = ws[j];
            a0 = fmaf(w, f0.x, a0); a1 = fmaf(w, f0.y, a1);
            a2 = fmaf(w, f1.x, a2); a3 = fmaf(w, f1.y, a3);
            a4 = fmaf(w, f2.x, a4); a5 = fmaf(w, f2.y, a5);
            a6 = fmaf(w, f3.x, a6); a7 = fmaf(w, f3.y, a7);
        }
        er = er_next;
    }

    uint4 o;
    *(__half2*)&o.x = __floats2half2_rn(a0, a1);
    *(__half2*)&o.y = __floats2half2_rn(a2, a3);
    *(__half2*)&o.z = __floats2half2_rn(a4, a5);
    *(__half2*)&o.w = __floats2half2_rn(a6, a7);
    cur[(size_t)v * 8 + sub] = o;
}

// ---------------------------------------------------------------------------
// Gate + combine. Warp per node; lane owns channels {2*lane, 2*lane+1}.
__global__ void __launch_bounds__(256)
k_gate(const float* __restrict__ feats, const float* __restrict__ s,
       float* __restrict__ out) {
    int v = blockIdx.x * 8 + (threadIdx.x >> 5);
    if (v >= NNODES) return;
    int lane = threadIdx.x & 31;

    float2 sv = *(const float2*)(s + 2 * lane);

    float2 h[KHOPS + 1];
    h[0] = *(const float2*)(feats + (size_t)v * DIM + 2 * lane);
#pragma unroll
    for (int k = 1; k <= KHOPS; k++)
        h[k] = __half22float2(
            g_H[(size_t)(k - 1) * NNODES * 32 + (size_t)v * 32 + lane]);

    float a0 = 0.f, a1 = 0.f;
#pragma unroll
    for (int k = 0; k <= KHOPS; k++) {
        float p = h[k].x * sv.x + h[k].y * sv.y;
#pragma unroll
        for (int o = 16; o; o >>= 1) p += __shfl_xor_sync(0xFFFFFFFFu, p, o);
        float g = 1.f / (1.f + __expf(-p));
        a0 = fmaf(g, h[k].x, a0);
        a1 = fmaf(g, h[k].y, a1);
    }
    float2 o2; o2.x = a0; o2.y = a1;
    *(float2*)(out + (size_t)v * DIM + 2 * lane) = o2;
}

// ---------------------------------------------------------------------------
extern "C" void kernel_launch(void* const* d_in, const int* in_sizes, int n_in,
                              void* d_out, int out_size) {
    const float* feats = (const float*)d_in[0];
    const float* s     = (const float*)d_in[1];
    const int*   src   = (const int*)d_in[2];
    const int*   dst   = (const int*)d_in[3];
    float*       out   = (float*)d_out;
    int nE = in_sizes[2];

    int nb = (NNODES + SCAN_B - 1) / SCAN_B;       // 98
    int eb = (nE + 255) / 256;
    int wb = (NNODES + 7) / 8;                     // 12500 (gate)
    int sb = (NNODES / 4 + 7) / 8;                 // 3125  (spmm)

    k_zero<<<(NNODES * 32 + 255) / 256, 256>>>(feats);
    k_count<<<eb, 256>>>(dst, nE);
    k_scan1<<<nb, SCAN_B>>>();
    k_scan2<<<1, 128>>>(nb, nE);
    k_scan3<<<nb, SCAN_B>>>();
    k_scatter<<<eb, 256>>>(src, dst, nE);

    for (int hop = 0; hop < KHOPS; hop++)
        k_spmm<<<sb, 256>>>(hop);

    k_gate<<<wb, 256>>>(feats, s, out);
}